// round 16
// baseline (speedup 1.0000x reference)
#include <cuda_runtime.h>
#include <cstdint>

#define BB   8
#define C    256
#define CI   128
#define NSP  3136
#define NCH  196
#define CHS  16
#define PN   4096
#define NT1  (NSP + 1)
#define NTILES (NSP / 64)              // 49
#define GEMM_BLOCKS (2 * NTILES * BB)  // 784

typedef unsigned long long u64;
typedef unsigned int u32;

// ---------------- f32x2 helpers ----------------
__device__ __forceinline__ u64 fma2(u64 a, u64 b, u64 c)
{
    u64 d;
    asm("fma.rn.f32x2 %0, %1, %2, %3;" : "=l"(d) : "l"(a), "l"(b), "l"(c));
    return d;
}
__device__ __forceinline__ u64 add2(u64 a, u64 b)
{
    u64 d;
    asm("add.rn.f32x2 %0, %1, %2;" : "=l"(d) : "l"(a), "l"(b));
    return d;
}
__device__ __forceinline__ u64 bcast2(float x)
{
    u64 d;
    asm("mov.b64 %0, {%1, %1};" : "=l"(d) : "r"(__float_as_uint(x)));
    return d;
}

// ---------------- scratch ----------------
__device__ float d_u[C];
__device__ float d_v[C];
__device__ float d_sc[C];
__device__ float d_obias[C];
__device__ float d_mb[C];
__device__ float d_ca;
__device__ float d_cb;
__device__ float d_MT[C * C];
__device__ float d_h[(size_t)BB * NSP * C];
__device__ float d_av[BB * NSP];
__device__ u64   d_skey[BB * NSP];
__device__ float d_bsort[BB * NSP];
__device__ int   d_perm[BB * NSP];
__device__ int   d_lbi[BB * NSP];
__device__ float d_cs0[BB * NCH * C];
__device__ float d_cs1[BB * NCH * C];
__device__ float2 d_T[(size_t)BB * NT1 * C];

// ---------------- MT = (wz @ g_w)^T  (+ prep in extra block) ----------------
__global__ void k_mt(const float* __restrict__ g_w,     const float* __restrict__ wz_w,
                     const float* __restrict__ theta_w, const float* __restrict__ theta_b,
                     const float* __restrict__ phi_w,   const float* __restrict__ phi_b,
                     const float* __restrict__ wf_w,    const float* __restrict__ wf_b,
                     const float* __restrict__ wz_b,    const float* __restrict__ g_b,
                     const float* __restrict__ gamma_,  const float* __restrict__ beta_,
                     const float* __restrict__ mean_,   const float* __restrict__ var_)
{
    int tid = threadIdx.x;
    if (blockIdx.x == 64) {
        int c = tid;
        float u = 0.f, v = 0.f, mb = 0.f;
        for (int o = 0; o < CI; o++) {
            u  = fmaf(wf_w[o],          theta_w[o * C + c], u);
            v  = fmaf(wf_w[CI + o],     phi_w[o * C + c],   v);
            mb = fmaf(wz_w[c * CI + o], g_b[o],              mb);
        }
        d_u[c] = u; d_v[c] = v; d_mb[c] = mb;
        float iv = gamma_[c] / sqrtf(var_[c] + 1e-5f);
        d_sc[c]    = iv * (1.0f / (float)NSP);
        d_obias[c] = (wz_b[c] - mean_[c]) * iv + beta_[c];
        if (c == 0) {
            float ca = 0.f, cb = 0.f;
            for (int o = 0; o < CI; o++) {
                ca = fmaf(wf_w[o],      theta_b[o], ca);
                cb = fmaf(wf_w[CI + o], phi_b[o],   cb);
            }
            d_ca = ca + wf_b[0];
            d_cb = cb;
        }
        return;
    }
    __shared__ float gcol[4][CI];
    int c0 = blockIdx.x * 4;
    for (int i = tid; i < 4 * CI; i += 256) {
        int j = i >> 7, o = i & 127;
        gcol[j][o] = g_w[o * C + c0 + j];
    }
    __syncthreads();
    int cc = tid;
    float a0 = 0.f, a1 = 0.f, a2 = 0.f, a3 = 0.f;
    for (int o = 0; o < CI; o++) {
        float w = wz_w[cc * CI + o];
        a0 = fmaf(w, gcol[0][o], a0);
        a1 = fmaf(w, gcol[1][o], a1);
        a2 = fmaf(w, gcol[2][o], a2);
        a3 = fmaf(w, gcol[3][o], a3);
    }
    d_MT[(c0 + 0) * C + cc] = a0;
    d_MT[(c0 + 1) * C + cc] = a1;
    d_MT[(c0 + 2) * C + cc] = a2;
    d_MT[(c0 + 3) * C + cc] = a3;
}

// ---------------- a/b + sort keys ----------------
__global__ void k_ab(const float* __restrict__ x)
{
    int b = blockIdx.y;
    int n = blockIdx.x * 256 + threadIdx.x;
    if (n >= NSP) return;
    const float* xp = x + (size_t)b * C * NSP + n;
    float a = d_ca, bb = d_cb;
#pragma unroll 8
    for (int c = 0; c < C; c++) {
        float xv = xp[(size_t)c * NSP];
        a  = fmaf(d_u[c], xv, a);
        bb = fmaf(d_v[c], xv, bb);
    }
    d_av[b * NSP + n] = a;
    u32 raw = __float_as_uint(bb);
    u32 key = ((int)raw < 0) ? ~raw : (raw | 0x80000000u);
    d_skey[b * NSP + n] = ((u64)key << 32) | (u64)(u32)n;
}

// ---------------- unified: blocks 0..7 sort, rest h-GEMM ----------------
__device__ __forceinline__ void cswap(u64& a, u64& b, bool up)
{
    if ((a > b) == up) { u64 t = a; a = b; b = t; }
}

__global__ void __launch_bounds__(256, 3) k_uni(const float* __restrict__ x)
{
    __shared__ __align__(16) char sraw[32768];   // 32KB union: sort keys / gemm tiles
    int bid = blockIdx.x;
    int tid = threadIdx.x;

    if (bid < BB) {
        // ================= SORT PATH =================
        u64* sbuf = reinterpret_cast<u64*>(sraw);
        int b = bid;
        for (int e = tid; e < PN; e += 256)
            sbuf[e] = (e < NSP) ? d_skey[b * NSP + e]
                                : (((u64)0xFFFFFFFFu << 32) | (u64)(u32)e);
        __syncthreads();

        for (int w = tid; w < PN / 8; w += 256) {
            u64 r[8];
#pragma unroll
            for (int i = 0; i < 8; i++) r[i] = sbuf[w * 8 + i];
            cswap(r[0], r[1], true);  cswap(r[2], r[3], false);
            cswap(r[4], r[5], true);  cswap(r[6], r[7], false);
            cswap(r[0], r[2], true);  cswap(r[1], r[3], true);
            cswap(r[4], r[6], false); cswap(r[5], r[7], false);
            cswap(r[0], r[1], true);  cswap(r[2], r[3], true);
            cswap(r[4], r[5], false); cswap(r[6], r[7], false);
            bool up8 = ((w & 1) == 0);
            cswap(r[0], r[4], up8); cswap(r[1], r[5], up8);
            cswap(r[2], r[6], up8); cswap(r[3], r[7], up8);
            cswap(r[0], r[2], up8); cswap(r[1], r[3], up8);
            cswap(r[4], r[6], up8); cswap(r[5], r[7], up8);
            cswap(r[0], r[1], up8); cswap(r[2], r[3], up8);
            cswap(r[4], r[5], up8); cswap(r[6], r[7], up8);
#pragma unroll
            for (int i = 0; i < 8; i++) sbuf[w * 8 + i] = r[i];
        }
        __syncthreads();

        for (int k = 16; k <= PN; k <<= 1) {
            for (int j = k >> 1; j >= 8; j >>= 1) {
#pragma unroll 4
                for (int t = tid; t < PN / 2; t += 256) {
                    int e  = ((t & ~(j - 1)) << 1) | (t & (j - 1));
                    int e2 = e + j;
                    bool up = ((e & k) == 0);
                    u64 a = sbuf[e], bq = sbuf[e2];
                    if ((a > bq) == up) { sbuf[e] = bq; sbuf[e2] = a; }
                }
                __syncthreads();
            }
            for (int w = tid; w < PN / 8; w += 256) {
                bool up = (((w * 8) & k) == 0);
                u64 r[8];
#pragma unroll
                for (int i = 0; i < 8; i++) r[i] = sbuf[w * 8 + i];
                cswap(r[0], r[4], up); cswap(r[1], r[5], up);
                cswap(r[2], r[6], up); cswap(r[3], r[7], up);
                cswap(r[0], r[2], up); cswap(r[1], r[3], up);
                cswap(r[4], r[6], up); cswap(r[5], r[7], up);
                cswap(r[0], r[1], up); cswap(r[2], r[3], up);
                cswap(r[4], r[5], up); cswap(r[6], r[7], up);
#pragma unroll
                for (int i = 0; i < 8; i++) sbuf[w * 8 + i] = r[i];
            }
            __syncthreads();
        }

        for (int e = tid; e < NSP; e += 256) {
            u64 v = sbuf[e];
            u32 hi = (u32)(v >> 32);
            u32 raw = (hi & 0x80000000u) ? (hi ^ 0x80000000u) : ~hi;
            d_bsort[b * NSP + e] = __uint_as_float(raw);
            d_perm[b * NSP + e]  = (int)(v & 0xFFFFFFFFu);
        }
        return;
    }

    // ========= GEMM PATH: 128cc(half) x 64n, thread 8cc x 4n, c-slab 32 =========
    float (*mt)[128] = reinterpret_cast<float(*)[128]>(sraw);          // 32x128 = 16KB
    float (*xs)[64]  = reinterpret_cast<float(*)[64]>(sraw + 16384);   // 32x64  = 8KB

    int g    = bid - BB;
    int half = g & 1;
    int rest = g >> 1;
    int n0   = (rest % NTILES) * 64;
    int b    = rest / NTILES;
    int lane = tid & 31, warp = tid >> 5;
    int wc = warp & 3, wn = warp >> 2;
    int lc = lane & 3, ln = lane >> 2;
    int ccb = wc * 32 + lc * 8;   // 8 cc per thread
    int nb  = wn * 32 + ln * 4;   // 4 n per thread

    u64 acc[4][4];
#pragma unroll
    for (int p = 0; p < 4; p++)
#pragma unroll
        for (int j = 0; j < 4; j++) acc[p][j] = 0ull;

    int mk = tid >> 3, mq = (tid & 7) * 16;   // mt: 32x128, 4 float4/thread
    int xk = tid >> 3, xq = (tid & 7) * 8;    // xs: 32x64,  2 float4/thread

    for (int c0 = 0; c0 < C; c0 += 32) {
#pragma unroll
        for (int i = 0; i < 4; i++)
            *reinterpret_cast<float4*>(&mt[mk][mq + i * 4]) =
                *reinterpret_cast<const float4*>(&d_MT[(c0 + mk) * C + half * 128 + mq + i * 4]);
#pragma unroll
        for (int i = 0; i < 2; i++)
            *reinterpret_cast<float4*>(&xs[xk][xq + i * 4]) =
                *reinterpret_cast<const float4*>(&x[((size_t)(b * C + c0 + xk)) * NSP + n0 + xq + i * 4]);
        __syncthreads();
#pragma unroll
        for (int k = 0; k < 32; k++) {
            ulonglong2 m01 = *reinterpret_cast<const ulonglong2*>(&mt[k][ccb]);
            ulonglong2 m23 = *reinterpret_cast<const ulonglong2*>(&mt[k][ccb + 4]);
            float4 xv = *reinterpret_cast<const float4*>(&xs[k][nb]);
            u64 xb0 = bcast2(xv.x), xb1 = bcast2(xv.y);
            u64 xb2 = bcast2(xv.z), xb3 = bcast2(xv.w);
            acc[0][0] = fma2(m01.x, xb0, acc[0][0]);
            acc[1][0] = fma2(m01.y, xb0, acc[1][0]);
            acc[2][0] = fma2(m23.x, xb0, acc[2][0]);
            acc[3][0] = fma2(m23.y, xb0, acc[3][0]);
            acc[0][1] = fma2(m01.x, xb1, acc[0][1]);
            acc[1][1] = fma2(m01.y, xb1, acc[1][1]);
            acc[2][1] = fma2(m23.x, xb1, acc[2][1]);
            acc[3][1] = fma2(m23.y, xb1, acc[3][1]);
            acc[0][2] = fma2(m01.x, xb2, acc[0][2]);
            acc[1][2] = fma2(m01.y, xb2, acc[1][2]);
            acc[2][2] = fma2(m23.x, xb2, acc[2][2]);
            acc[3][2] = fma2(m23.y, xb2, acc[3][2]);
            acc[0][3] = fma2(m01.x, xb3, acc[0][3]);
            acc[1][3] = fma2(m01.y, xb3, acc[1][3]);
            acc[2][3] = fma2(m23.x, xb3, acc[2][3]);
            acc[3][3] = fma2(m23.y, xb3, acc[3][3]);
        }
        __syncthreads();
    }

    ulonglong2 mb01 = *reinterpret_cast<const ulonglong2*>(&d_mb[half * 128 + ccb]);
    ulonglong2 mb23 = *reinterpret_cast<const ulonglong2*>(&d_mb[half * 128 + ccb + 4]);
#pragma unroll
    for (int j = 0; j < 4; j++) {
        int n = n0 + nb + j;
        float* hp = &d_h[((size_t)b * NSP + n) * C + half * 128 + ccb];
        ulonglong2 r0 = make_ulonglong2(add2(acc[0][j], mb01.x), add2(acc[1][j], mb01.y));
        ulonglong2 r1 = make_ulonglong2(add2(acc[2][j], mb23.x), add2(acc[3][j], mb23.y));
        *reinterpret_cast<ulonglong2*>(hp)     = r0;
        *reinterpret_cast<ulonglong2*>(hp + 4) = r1;
    }
}

// ---------------- chunk totals (+ fused binary search) ----------------
__global__ void k_suf1()
{
    __shared__ int sp[CHS];
    __shared__ float sb[CHS];
    int b = blockIdx.y, ch = blockIdx.x, cc = threadIdx.x;

    int gid = (blockIdx.y * NCH + blockIdx.x) * 256 + cc;
    if (gid < BB * NSP) {
        int sbb = gid / NSP;
        float keyv = -d_av[gid];
        const float* sbp = d_bsort + sbb * NSP;
        int lo = 0, hi = NSP;
        while (lo < hi) {
            int mid = (lo + hi) >> 1;
            if (__ldg(sbp + mid) > keyv) hi = mid; else lo = mid + 1;
        }
        d_lbi[gid] = lo;
    }

    int base = b * NSP + ch * CHS;
    if (cc < CHS) { sp[cc] = d_perm[base + cc]; sb[cc] = d_bsort[base + cc]; }
    __syncthreads();
    float s0 = 0.f, s1 = 0.f;
#pragma unroll 4
    for (int r = 0; r < CHS; r++) {
        float g = d_h[((size_t)b * NSP + sp[r]) * C + cc];
        s0 += g;
        s1 = fmaf(sb[r], g, s1);
    }
    d_cs0[(b * NCH + ch) * C + cc] = s0;
    d_cs1[(b * NCH + ch) * C + cc] = s1;
}

// ---------------- full suffix arrays (self-computed exclusive scan) ----------------
__global__ void k_suf3()
{
    __shared__ int sp[CHS];
    __shared__ float sb[CHS];
    int b = blockIdx.y, ch = blockIdx.x, cc = threadIdx.x;
    int base = b * NSP + ch * CHS;
    if (cc < CHS) { sp[cc] = d_perm[base + cc]; sb[cc] = d_bsort[base + cc]; }
    __syncthreads();

    float a0 = 0.f, a1 = 0.f;
    for (int cp = ch + 1; cp < NCH; cp++) {
        a0 += d_cs0[(b * NCH + cp) * C + cc];
        a1 += d_cs1[(b * NCH + cp) * C + cc];
    }
    if (ch == NCH - 1)
        d_T[((size_t)b * NT1 + NSP) * C + cc] = make_float2(0.f, 0.f);

    for (int r = CHS - 1; r >= 0; --r) {
        int rr = ch * CHS + r;
        float g = d_h[((size_t)b * NSP + sp[r]) * C + cc];
        a0 += g;
        a1 = fmaf(sb[r], g, a1);
        d_T[((size_t)b * NT1 + rr) * C + cc] = make_float2(a0, a1);
    }
}

// ---------------- output ----------------
__global__ void __launch_bounds__(256) k_out(const float* __restrict__ x,
                                             float* __restrict__ out)
{
    __shared__ float zt[C][33];
    __shared__ float tl[32];
    __shared__ int lbl[32];
    int b = blockIdx.y, n0 = blockIdx.x * 32;
    int tid = threadIdx.x, lane = tid & 31, warp = tid >> 5;
    if (tid < 32) {
        tl[tid]  = d_av[b * NSP + n0 + tid];
        lbl[tid] = d_lbi[b * NSP + n0 + tid];
    }
    __syncthreads();
#pragma unroll
    for (int s = 0; s < 4; s++) {
        int nn = warp + s * 8;
        float t = tl[nn];
        size_t base = ((size_t)b * NT1 + lbl[nn]) * C;
#pragma unroll
        for (int it = 0; it < 8; it++) {
            int cc = it * 32 + lane;
            float2 T = d_T[base + cc];
            zt[cc][nn] = fmaf(fmaf(t, T.x, T.y), d_sc[cc], d_obias[cc]);
        }
    }
    __syncthreads();
#pragma unroll 4
    for (int r = 0; r < 32; r++) {
        int cc = warp * 32 + r;
        size_t g = ((size_t)(b * C + cc)) * NSP + n0 + lane;
        out[g] = zt[cc][lane] + x[g];
    }
}

// ---------------- launch ----------------
extern "C" void kernel_launch(void* const* d_in, const int* in_sizes, int n_in,
                              void* d_out, int out_size)
{
    const float* x       = (const float*)d_in[0];
    const float* g_w     = (const float*)d_in[1];
    const float* g_b     = (const float*)d_in[2];
    const float* theta_w = (const float*)d_in[3];
    const float* theta_b = (const float*)d_in[4];
    const float* phi_w   = (const float*)d_in[5];
    const float* phi_b   = (const float*)d_in[6];
    const float* wf_w    = (const float*)d_in[7];
    const float* wf_b    = (const float*)d_in[8];
    const float* wz_w    = (const float*)d_in[9];
    const float* wz_b    = (const float*)d_in[10];
    const float* bn_g    = (const float*)d_in[11];
    const float* bn_b    = (const float*)d_in[12];
    const float* bn_m    = (const float*)d_in[13];
    const float* bn_v    = (const float*)d_in[14];
    float* out = (float*)d_out;

    k_mt<<<65, 256>>>(g_w, wz_w, theta_w, theta_b, phi_w, phi_b,
                      wf_w, wf_b, wz_b, g_b, bn_g, bn_b, bn_m, bn_v);
    k_ab<<<dim3((NSP + 255) / 256, BB), 256>>>(x);
    k_uni<<<BB + GEMM_BLOCKS, 256>>>(x);
    k_suf1<<<dim3(NCH, BB), 256>>>();
    k_suf3<<<dim3(NCH, BB), 256>>>();
    k_out<<<dim3(NSP / 32, BB), 256>>>(x, out);
}

// round 17
// speedup vs baseline: 1.2280x; 1.2280x over previous
#include <cuda_runtime.h>
#include <cstdint>

#define BB   8
#define C    256
#define CI   128
#define NSP  3136
#define NCH  98
#define CHS  32
#define PN   4096
#define NT1  (NSP + 1)
#define NTILES (NSP / 64)              // 49
#define GEMM_BLOCKS (2 * NTILES * BB)  // 784
#define ABPB 13                        // ab blocks per batch (13*256 >= 3136)

typedef unsigned long long u64;
typedef unsigned int u32;

// ---------------- f32x2 helpers ----------------
__device__ __forceinline__ u64 fma2(u64 a, u64 b, u64 c)
{
    u64 d;
    asm("fma.rn.f32x2 %0, %1, %2, %3;" : "=l"(d) : "l"(a), "l"(b), "l"(c));
    return d;
}
__device__ __forceinline__ u64 add2(u64 a, u64 b)
{
    u64 d;
    asm("add.rn.f32x2 %0, %1, %2;" : "=l"(d) : "l"(a), "l"(b));
    return d;
}
__device__ __forceinline__ u64 bcast2(float x)
{
    u64 d;
    asm("mov.b64 %0, {%1, %1};" : "=l"(d) : "r"(__float_as_uint(x)));
    return d;
}

// ---------------- scratch ----------------
__device__ float d_u[C];
__device__ float d_v[C];
__device__ float d_sc[C];
__device__ float d_obias[C];
__device__ float d_mb[C];
__device__ float d_ca;
__device__ float d_cb;
__device__ float d_MT[C * C];
__device__ float d_h[(size_t)BB * NSP * C];
__device__ float d_av[BB * NSP];
__device__ u64   d_skey[BB * NSP];
__device__ float d_bsort[BB * NSP];
__device__ int   d_perm[BB * NSP];
__device__ int   d_lbi[BB * NSP];
__device__ float d_cs0[BB * NCH * C];
__device__ float d_cs1[BB * NCH * C];
__device__ float2 d_T[(size_t)BB * NT1 * C];

// ---------------- MT + prep + a/b keys, one launch ----------------
// blocks 0..63: MT = (wz@g_w)^T ; block 64: prep ; blocks 65..168: a/b keys
__global__ void k_mt(const float* __restrict__ g_w,     const float* __restrict__ wz_w,
                     const float* __restrict__ theta_w, const float* __restrict__ theta_b,
                     const float* __restrict__ phi_w,   const float* __restrict__ phi_b,
                     const float* __restrict__ wf_w,    const float* __restrict__ wf_b,
                     const float* __restrict__ wz_b,    const float* __restrict__ g_b,
                     const float* __restrict__ gamma_,  const float* __restrict__ beta_,
                     const float* __restrict__ mean_,   const float* __restrict__ var_,
                     const float* __restrict__ x)
{
    int tid = threadIdx.x;
    int bid = blockIdx.x;

    if (bid == 64) {
        // ---- prep path (globals used by later kernels) ----
        int c = tid;
        float u = 0.f, v = 0.f, mb = 0.f;
        for (int o = 0; o < CI; o++) {
            u  = fmaf(wf_w[o],          theta_w[o * C + c], u);
            v  = fmaf(wf_w[CI + o],     phi_w[o * C + c],   v);
            mb = fmaf(wz_w[c * CI + o], g_b[o],              mb);
        }
        d_u[c] = u; d_v[c] = v; d_mb[c] = mb;
        float iv = gamma_[c] / sqrtf(var_[c] + 1e-5f);
        d_sc[c]    = iv * (1.0f / (float)NSP);
        d_obias[c] = (wz_b[c] - mean_[c]) * iv + beta_[c];
        if (c == 0) {
            float ca = 0.f, cb = 0.f;
            for (int o = 0; o < CI; o++) {
                ca = fmaf(wf_w[o],      theta_b[o], ca);
                cb = fmaf(wf_w[CI + o], phi_b[o],   cb);
            }
            d_ca = ca + wf_b[0];
            d_cb = cb;
        }
        return;
    }

    if (bid > 64) {
        // ---- a/b path: self-contained (recomputes u/v/ca/cb into smem) ----
        __shared__ float su[C];
        __shared__ float sv[C];
        __shared__ float sca, scb;
        {
            int c = tid;
            float u = 0.f, v = 0.f;
            for (int o = 0; o < CI; o++) {
                u = fmaf(wf_w[o],      theta_w[o * C + c], u);
                v = fmaf(wf_w[CI + o], phi_w[o * C + c],   v);
            }
            su[c] = u; sv[c] = v;
            if (c == 0) {
                float ca = 0.f, cb = 0.f;
                for (int o = 0; o < CI; o++) {
                    ca = fmaf(wf_w[o],      theta_b[o], ca);
                    cb = fmaf(wf_w[CI + o], phi_b[o],   cb);
                }
                sca = ca + wf_b[0];
                scb = cb;
            }
        }
        __syncthreads();

        int seg = bid - 65;            // 0..103
        int b   = seg / ABPB;
        int n   = (seg % ABPB) * 256 + tid;
        if (n >= NSP) return;
        const float* xp = x + (size_t)b * C * NSP + n;
        float a = sca, bb = scb;
#pragma unroll 8
        for (int c = 0; c < C; c++) {
            float xv = xp[(size_t)c * NSP];
            a  = fmaf(su[c], xv, a);
            bb = fmaf(sv[c], xv, bb);
        }
        d_av[b * NSP + n] = a;
        u32 raw = __float_as_uint(bb);
        u32 key = ((int)raw < 0) ? ~raw : (raw | 0x80000000u);
        d_skey[b * NSP + n] = ((u64)key << 32) | (u64)(u32)n;
        return;
    }

    // ---- MT path ----
    __shared__ float gcol[4][CI];
    int c0 = bid * 4;
    for (int i = tid; i < 4 * CI; i += 256) {
        int j = i >> 7, o = i & 127;
        gcol[j][o] = g_w[o * C + c0 + j];
    }
    __syncthreads();
    int cc = tid;
    float a0 = 0.f, a1 = 0.f, a2 = 0.f, a3 = 0.f;
    for (int o = 0; o < CI; o++) {
        float w = wz_w[cc * CI + o];
        a0 = fmaf(w, gcol[0][o], a0);
        a1 = fmaf(w, gcol[1][o], a1);
        a2 = fmaf(w, gcol[2][o], a2);
        a3 = fmaf(w, gcol[3][o], a3);
    }
    d_MT[(c0 + 0) * C + cc] = a0;
    d_MT[(c0 + 1) * C + cc] = a1;
    d_MT[(c0 + 2) * C + cc] = a2;
    d_MT[(c0 + 3) * C + cc] = a3;
}

// ---------------- unified: blocks 0..7 sort, rest h-GEMM ----------------
__device__ __forceinline__ void cswap(u64& a, u64& b, bool up)
{
    if ((a > b) == up) { u64 t = a; a = b; b = t; }
}

__global__ void __launch_bounds__(256, 3) k_uni(const float* __restrict__ x)
{
    __shared__ __align__(16) char sraw[32768];   // 32KB union: sort keys / gemm tiles
    int bid = blockIdx.x;
    int tid = threadIdx.x;

    if (bid < BB) {
        // ================= SORT PATH =================
        u64* sbuf = reinterpret_cast<u64*>(sraw);
        int b = bid;
        for (int e = tid; e < PN; e += 256)
            sbuf[e] = (e < NSP) ? d_skey[b * NSP + e]
                                : (((u64)0xFFFFFFFFu << 32) | (u64)(u32)e);
        __syncthreads();

        for (int w = tid; w < PN / 8; w += 256) {
            u64 r[8];
#pragma unroll
            for (int i = 0; i < 8; i++) r[i] = sbuf[w * 8 + i];
            cswap(r[0], r[1], true);  cswap(r[2], r[3], false);
            cswap(r[4], r[5], true);  cswap(r[6], r[7], false);
            cswap(r[0], r[2], true);  cswap(r[1], r[3], true);
            cswap(r[4], r[6], false); cswap(r[5], r[7], false);
            cswap(r[0], r[1], true);  cswap(r[2], r[3], true);
            cswap(r[4], r[5], false); cswap(r[6], r[7], false);
            bool up8 = ((w & 1) == 0);
            cswap(r[0], r[4], up8); cswap(r[1], r[5], up8);
            cswap(r[2], r[6], up8); cswap(r[3], r[7], up8);
            cswap(r[0], r[2], up8); cswap(r[1], r[3], up8);
            cswap(r[4], r[6], up8); cswap(r[5], r[7], up8);
            cswap(r[0], r[1], up8); cswap(r[2], r[3], up8);
            cswap(r[4], r[5], up8); cswap(r[6], r[7], up8);
#pragma unroll
            for (int i = 0; i < 8; i++) sbuf[w * 8 + i] = r[i];
        }
        __syncthreads();

        for (int k = 16; k <= PN; k <<= 1) {
            for (int j = k >> 1; j >= 8; j >>= 1) {
#pragma unroll 4
                for (int t = tid; t < PN / 2; t += 256) {
                    int e  = ((t & ~(j - 1)) << 1) | (t & (j - 1));
                    int e2 = e + j;
                    bool up = ((e & k) == 0);
                    u64 a = sbuf[e], bq = sbuf[e2];
                    if ((a > bq) == up) { sbuf[e] = bq; sbuf[e2] = a; }
                }
                __syncthreads();
            }
            for (int w = tid; w < PN / 8; w += 256) {
                bool up = (((w * 8) & k) == 0);
                u64 r[8];
#pragma unroll
                for (int i = 0; i < 8; i++) r[i] = sbuf[w * 8 + i];
                cswap(r[0], r[4], up); cswap(r[1], r[5], up);
                cswap(r[2], r[6], up); cswap(r[3], r[7], up);
                cswap(r[0], r[2], up); cswap(r[1], r[3], up);
                cswap(r[4], r[6], up); cswap(r[5], r[7], up);
                cswap(r[0], r[1], up); cswap(r[2], r[3], up);
                cswap(r[4], r[5], up); cswap(r[6], r[7], up);
#pragma unroll
                for (int i = 0; i < 8; i++) sbuf[w * 8 + i] = r[i];
            }
            __syncthreads();
        }

        for (int e = tid; e < NSP; e += 256) {
            u64 v = sbuf[e];
            u32 hi = (u32)(v >> 32);
            u32 raw = (hi & 0x80000000u) ? (hi ^ 0x80000000u) : ~hi;
            d_bsort[b * NSP + e] = __uint_as_float(raw);
            d_perm[b * NSP + e]  = (int)(v & 0xFFFFFFFFu);
        }
        return;
    }

    // ========= GEMM PATH: 128cc(half) x 64n, thread 8cc x 4n, c-slab 32 =========
    float (*mt)[128] = reinterpret_cast<float(*)[128]>(sraw);          // 32x128 = 16KB
    float (*xs)[64]  = reinterpret_cast<float(*)[64]>(sraw + 16384);   // 32x64  = 8KB

    int g    = bid - BB;
    int half = g & 1;
    int rest = g >> 1;
    int n0   = (rest % NTILES) * 64;
    int b    = rest / NTILES;
    int lane = tid & 31, warp = tid >> 5;
    int wc = warp & 3, wn = warp >> 2;
    int lc = lane & 3, ln = lane >> 2;
    int ccb = wc * 32 + lc * 8;   // 8 cc per thread
    int nb  = wn * 32 + ln * 4;   // 4 n per thread

    u64 acc[4][4];
#pragma unroll
    for (int p = 0; p < 4; p++)
#pragma unroll
        for (int j = 0; j < 4; j++) acc[p][j] = 0ull;

    int mk = tid >> 3, mq = (tid & 7) * 16;   // mt: 32x128, 4 float4/thread
    int xk = tid >> 3, xq = (tid & 7) * 8;    // xs: 32x64,  2 float4/thread

    for (int c0 = 0; c0 < C; c0 += 32) {
#pragma unroll
        for (int i = 0; i < 4; i++)
            *reinterpret_cast<float4*>(&mt[mk][mq + i * 4]) =
                *reinterpret_cast<const float4*>(&d_MT[(c0 + mk) * C + half * 128 + mq + i * 4]);
#pragma unroll
        for (int i = 0; i < 2; i++)
            *reinterpret_cast<float4*>(&xs[xk][xq + i * 4]) =
                *reinterpret_cast<const float4*>(&x[((size_t)(b * C + c0 + xk)) * NSP + n0 + xq + i * 4]);
        __syncthreads();
#pragma unroll
        for (int k = 0; k < 32; k++) {
            ulonglong2 m01 = *reinterpret_cast<const ulonglong2*>(&mt[k][ccb]);
            ulonglong2 m23 = *reinterpret_cast<const ulonglong2*>(&mt[k][ccb + 4]);
            float4 xv = *reinterpret_cast<const float4*>(&xs[k][nb]);
            u64 xb0 = bcast2(xv.x), xb1 = bcast2(xv.y);
            u64 xb2 = bcast2(xv.z), xb3 = bcast2(xv.w);
            acc[0][0] = fma2(m01.x, xb0, acc[0][0]);
            acc[1][0] = fma2(m01.y, xb0, acc[1][0]);
            acc[2][0] = fma2(m23.x, xb0, acc[2][0]);
            acc[3][0] = fma2(m23.y, xb0, acc[3][0]);
            acc[0][1] = fma2(m01.x, xb1, acc[0][1]);
            acc[1][1] = fma2(m01.y, xb1, acc[1][1]);
            acc[2][1] = fma2(m23.x, xb1, acc[2][1]);
            acc[3][1] = fma2(m23.y, xb1, acc[3][1]);
            acc[0][2] = fma2(m01.x, xb2, acc[0][2]);
            acc[1][2] = fma2(m01.y, xb2, acc[1][2]);
            acc[2][2] = fma2(m23.x, xb2, acc[2][2]);
            acc[3][2] = fma2(m23.y, xb2, acc[3][2]);
            acc[0][3] = fma2(m01.x, xb3, acc[0][3]);
            acc[1][3] = fma2(m01.y, xb3, acc[1][3]);
            acc[2][3] = fma2(m23.x, xb3, acc[2][3]);
            acc[3][3] = fma2(m23.y, xb3, acc[3][3]);
        }
        __syncthreads();
    }

    ulonglong2 mb01 = *reinterpret_cast<const ulonglong2*>(&d_mb[half * 128 + ccb]);
    ulonglong2 mb23 = *reinterpret_cast<const ulonglong2*>(&d_mb[half * 128 + ccb + 4]);
#pragma unroll
    for (int j = 0; j < 4; j++) {
        int n = n0 + nb + j;
        float* hp = &d_h[((size_t)b * NSP + n) * C + half * 128 + ccb];
        ulonglong2 r0 = make_ulonglong2(add2(acc[0][j], mb01.x), add2(acc[1][j], mb01.y));
        ulonglong2 r1 = make_ulonglong2(add2(acc[2][j], mb23.x), add2(acc[3][j], mb23.y));
        *reinterpret_cast<ulonglong2*>(hp)     = r0;
        *reinterpret_cast<ulonglong2*>(hp + 4) = r1;
    }
}

// ---------------- chunk totals (+ fused binary search) ----------------
__global__ void k_suf1()
{
    __shared__ int sp[CHS];
    __shared__ float sb[CHS];
    int b = blockIdx.y, ch = blockIdx.x, cc = threadIdx.x;

    int gid = (blockIdx.y * NCH + blockIdx.x) * 256 + cc;
    if (gid < BB * NSP) {
        int sbb = gid / NSP;
        float keyv = -d_av[gid];
        const float* sbp = d_bsort + sbb * NSP;
        int lo = 0, hi = NSP;
        while (lo < hi) {
            int mid = (lo + hi) >> 1;
            if (__ldg(sbp + mid) > keyv) hi = mid; else lo = mid + 1;
        }
        d_lbi[gid] = lo;
    }

    int base = b * NSP + ch * CHS;
    if (cc < CHS) { sp[cc] = d_perm[base + cc]; sb[cc] = d_bsort[base + cc]; }
    __syncthreads();
    float s0 = 0.f, s1 = 0.f;
#pragma unroll 4
    for (int r = 0; r < CHS; r++) {
        float g = d_h[((size_t)b * NSP + sp[r]) * C + cc];
        s0 += g;
        s1 = fmaf(sb[r], g, s1);
    }
    d_cs0[(b * NCH + ch) * C + cc] = s0;
    d_cs1[(b * NCH + ch) * C + cc] = s1;
}

// ---------------- full suffix arrays (self-computed exclusive scan) ----------------
__global__ void k_suf3()
{
    __shared__ int sp[CHS];
    __shared__ float sb[CHS];
    int b = blockIdx.y, ch = blockIdx.x, cc = threadIdx.x;
    int base = b * NSP + ch * CHS;
    if (cc < CHS) { sp[cc] = d_perm[base + cc]; sb[cc] = d_bsort[base + cc]; }
    __syncthreads();

    float a0 = 0.f, a1 = 0.f;
    for (int cp = ch + 1; cp < NCH; cp++) {
        a0 += d_cs0[(b * NCH + cp) * C + cc];
        a1 += d_cs1[(b * NCH + cp) * C + cc];
    }
    if (ch == NCH - 1)
        d_T[((size_t)b * NT1 + NSP) * C + cc] = make_float2(0.f, 0.f);

    for (int r = CHS - 1; r >= 0; --r) {
        int rr = ch * CHS + r;
        float g = d_h[((size_t)b * NSP + sp[r]) * C + cc];
        a0 += g;
        a1 = fmaf(sb[r], g, a1);
        d_T[((size_t)b * NT1 + rr) * C + cc] = make_float2(a0, a1);
    }
}

// ---------------- output ----------------
__global__ void __launch_bounds__(256) k_out(const float* __restrict__ x,
                                             float* __restrict__ out)
{
    __shared__ float zt[C][33];
    __shared__ float tl[32];
    __shared__ int lbl[32];
    int b = blockIdx.y, n0 = blockIdx.x * 32;
    int tid = threadIdx.x, lane = tid & 31, warp = tid >> 5;
    if (tid < 32) {
        tl[tid]  = d_av[b * NSP + n0 + tid];
        lbl[tid] = d_lbi[b * NSP + n0 + tid];
    }
    __syncthreads();
#pragma unroll
    for (int s = 0; s < 4; s++) {
        int nn = warp + s * 8;
        float t = tl[nn];
        size_t base = ((size_t)b * NT1 + lbl[nn]) * C;
#pragma unroll
        for (int it = 0; it < 8; it++) {
            int cc = it * 32 + lane;
            float2 T = d_T[base + cc];
            zt[cc][nn] = fmaf(fmaf(t, T.x, T.y), d_sc[cc], d_obias[cc]);
        }
    }
    __syncthreads();
#pragma unroll 4
    for (int r = 0; r < 32; r++) {
        int cc = warp * 32 + r;
        size_t g = ((size_t)(b * C + cc)) * NSP + n0 + lane;
        out[g] = zt[cc][lane] + x[g];
    }
}

// ---------------- launch ----------------
extern "C" void kernel_launch(void* const* d_in, const int* in_sizes, int n_in,
                              void* d_out, int out_size)
{
    const float* x       = (const float*)d_in[0];
    const float* g_w     = (const float*)d_in[1];
    const float* g_b     = (const float*)d_in[2];
    const float* theta_w = (const float*)d_in[3];
    const float* theta_b = (const float*)d_in[4];
    const float* phi_w   = (const float*)d_in[5];
    const float* phi_b   = (const float*)d_in[6];
    const float* wf_w    = (const float*)d_in[7];
    const float* wf_b    = (const float*)d_in[8];
    const float* wz_w    = (const float*)d_in[9];
    const float* wz_b    = (const float*)d_in[10];
    const float* bn_g    = (const float*)d_in[11];
    const float* bn_b    = (const float*)d_in[12];
    const float* bn_m    = (const float*)d_in[13];
    const float* bn_v    = (const float*)d_in[14];
    float* out = (float*)d_out;

    k_mt<<<65 + BB * ABPB, 256>>>(g_w, wz_w, theta_w, theta_b, phi_w, phi_b,
                                  wf_w, wf_b, wz_b, g_b, bn_g, bn_b, bn_m, bn_v, x);
    k_uni<<<BB + GEMM_BLOCKS, 256>>>(x);
    k_suf1<<<dim3(NCH, BB), 256>>>();
    k_suf3<<<dim3(NCH, BB), 256>>>();
    k_out<<<dim3(NSP / 32, BB), 256>>>(x, out);
}